// round 9
// baseline (speedup 1.0000x reference)
#include <cuda_runtime.h>
#include <cstdint>
#include <math.h>

// ---------------------------------------------------------------------------
// GigaMesher9000 round 9.
//   guard1 (no output-ReLU crossing): out = base + ((s.*p)@M)*invc   (exact)
//   guard2 (|g|*invc provably < 2e-4 * min|base|): out = base (const fill)
// Pass1 computes per-row squared norms via Cholesky quadratic form:
//   ||hW+b||^2 = ||L^T h + w||^2 + d,  G=WW^T=LL^T, w=L^{-1}(Wb^T), d=|b|^2-|w|^2
// and bounds row-sum |s_o p_o| by Cauchy-Schwarz: <= ||s_row||*||p_row||.
// Modes: 2 = const fill (bulk-copy, one wave), 1 = linear recompute, 0 = exact.
// 4 launches: k_setup (chol packs) -> k_pass1 (reduction + finalize in last
// block) -> k_fill (mode2) -> k_fallback (mode 0/1, early exit otherwise).
// ---------------------------------------------------------------------------

#define MAXN    2000000
#define P1THR   128
#define P2THR   256
#define FILLBLK 148
#define FBBLK   296
#define CHUNKB  12288       // bulk-fill chunk: multiple of 48 and 16
#define CHUNKF  (CHUNKB / 4)

typedef unsigned long long ull;

// ---- packed f32x2 helpers --------------------------------------------------
__device__ __forceinline__ ull pk2(float lo, float hi) {
    ull r; asm("mov.b64 %0,{%1,%2};" : "=l"(r) : "f"(lo), "f"(hi)); return r;
}
__device__ __forceinline__ void upk2(ull v, float& lo, float& hi) {
    asm("mov.b64 {%0,%1},%2;" : "=f"(lo), "=f"(hi) : "l"(v));
}
__device__ __forceinline__ ull dup2(float w) {
    ull r; asm("mov.b64 %0,{%1,%1};" : "=l"(r) : "f"(w)); return r;
}
__device__ __forceinline__ ull fma2(ull a, ull b, ull c) {
    ull d; asm("fma.rn.f32x2 %0,%1,%2,%3;" : "=l"(d) : "l"(a), "l"(b), "l"(c)); return d;
}
__device__ __forceinline__ ull mul2(ull a, ull b) {
    ull d; asm("mul.rn.f32x2 %0,%1,%2;" : "=l"(d) : "l"(a), "l"(b)); return d;
}

// ---- device-global accumulators / constants -------------------------------
__device__ double        g_ss;             // zero at load; re-zeroed by finalize
__device__ double        g_pp;
__device__ unsigned int  g_rowmax_bits;    // max over rows of ssr*ppr (squared)
__device__ unsigned int  g_count;
__device__ float         g_M[30];          // [10][3] (mode-1 fallback)
__device__ float         g_base[3];
__device__ float         g_minabs_ob1;
__device__ float         g_maxabs_ow1;
__device__ float         g_maxabsM;
__device__ float         g_minabs_base;
__device__ int           g_mode;
__device__ float         g_invc;
__device__ float         g_CS[66];         // s-branch chol pack: per i {w_i, L[i..9][i]}, [65]=d
__device__ float         g_CP[66];         // p-branch chol pack

// ---------------------------------------------------------------------------
// Cholesky of G+eps*I, forward solve, pack for the row-block inner loop.
// ---------------------------------------------------------------------------
__device__ void chol_pack(const float* G, const float* v, float c, float* out)
{
    float L[10][10];
    float md = 0.f;
    for (int j = 0; j < 10; j++) md = fmaxf(md, G[j * 10 + j]);
    float eps = 1e-6f * md + 1e-30f;
    for (int j = 0; j < 10; j++) {
        float s = G[j * 10 + j] + eps;
        for (int k = 0; k < j; k++) s -= L[j][k] * L[j][k];
        s = fmaxf(s, 1e-30f);
        float dj = sqrtf(s);
        L[j][j] = dj;
        float inv = 1.0f / dj;
        for (int i = j + 1; i < 10; i++) {
            float t = G[i * 10 + j];
            for (int k = 0; k < j; k++) t -= L[i][k] * L[j][k];
            L[i][j] = t * inv;
        }
    }
    float w[10];
    for (int i = 0; i < 10; i++) {
        float t = v[i];
        for (int k = 0; k < i; k++) t -= L[i][k] * w[k];
        w[i] = t / L[i][i];
    }
    float d = c;
    for (int i = 0; i < 10; i++) d -= w[i] * w[i];
    int k = 0;
    for (int i = 0; i < 10; i++) {
        out[k++] = w[i];
        for (int j = i; j < 10; j++) out[k++] = L[j][i];
    }
    out[65] = d;
}

// ---------------------------------------------------------------------------
// Setup: M, base, guard constants, Gram matrices + Cholesky packs.
// ---------------------------------------------------------------------------
__global__ void k_setup(const float* __restrict__ sw2, const float* __restrict__ sb2,
                        const float* __restrict__ pw2, const float* __restrict__ pb2,
                        const float* __restrict__ ow1, const float* __restrict__ ob1,
                        const float* __restrict__ ow2, const float* __restrict__ ob2)
{
    __shared__ float Gs[100], Gp[100], vsv[10], vpv[10], csc[2];
    __shared__ float aM[30], bsv[3];
    int tid = threadIdx.x;

    if (tid < 30) {                        // M[i][k]
        int i = tid / 3, k = tid % 3;
        float acc = 0.f;
        for (int j = 0; j < 100; j++) {
            float o = ob1[j];
            if (o > 0.f) acc = fmaf(ow1[i * 100 + j], ow2[j * 3 + k], acc);
        }
        g_M[tid] = acc;
        aM[tid] = fabsf(acc);
    } else if (tid < 33) {                 // base[k]
        int k = tid - 30;
        float acc = ob2[k];
        for (int j = 0; j < 100; j++)
            acc = fmaf(fmaxf(ob1[j], 0.f), ow2[j * 3 + k], acc);
        g_base[k] = acc;
        bsv[k] = fabsf(acc);
    }
    if (tid >= 64 && tid < 96) {           // max|ow1|
        int lane = tid - 64;
        float m = 0.f;
        for (int j = lane; j < 1000; j += 32) m = fmaxf(m, fabsf(ow1[j]));
        #pragma unroll
        for (int o = 16; o > 0; o >>= 1)
            m = fmaxf(m, __shfl_down_sync(0xffffffffu, m, o));
        if (lane == 0) g_maxabs_ow1 = m;
    }
    if (tid >= 96) {                       // min|ob1|
        int lane = tid - 96;
        float m = 3.0e38f;
        for (int j = lane; j < 100; j += 32) m = fminf(m, fabsf(ob1[j]));
        #pragma unroll
        for (int o = 16; o > 0; o >>= 1)
            m = fminf(m, __shfl_down_sync(0xffffffffu, m, o));
        if (lane == 0) g_minabs_ob1 = m;
    }

    // Gram matrices / bias projections (disjoint work, may overlap above)
    if (tid < 100) {
        int i = tid / 10, j = tid % 10;
        float gs = 0.f, gp = 0.f;
        for (int o = 0; o < 10; o++) {
            gs = fmaf(sw2[i * 10 + o], sw2[j * 10 + o], gs);
            gp = fmaf(pw2[i * 10 + o], pw2[j * 10 + o], gp);
        }
        Gs[tid] = gs; Gp[tid] = gp;
    }
    if (tid >= 100 && tid < 110) {
        int i = tid - 100;
        float vs = 0.f, vp = 0.f;
        for (int o = 0; o < 10; o++) {
            vs = fmaf(sw2[i * 10 + o], sb2[o], vs);
            vp = fmaf(pw2[i * 10 + o], pb2[o], vp);
        }
        vsv[i] = vs; vpv[i] = vp;
    }
    if (tid == 110) {
        float cs = 0.f, cp = 0.f;
        for (int o = 0; o < 10; o++) { cs = fmaf(sb2[o], sb2[o], cs); cp = fmaf(pb2[o], pb2[o], cp); }
        csc[0] = cs; csc[1] = cp;
    }
    __syncthreads();

    if (tid == 0)  chol_pack(Gs, vsv, csc[0], g_CS);
    if (tid == 32) chol_pack(Gp, vpv, csc[1], g_CP);
    if (tid == 1) {
        float mm = 0.f;
        #pragma unroll
        for (int i = 0; i < 30; i++) mm = fmaxf(mm, aM[i]);
        g_maxabsM = mm;
        g_minabs_base = fminf(bsv[0], fminf(bsv[1], bsv[2]));
    }
}

// ---------------------------------------------------------------------------
// Packed quadratic form: ss = d + ||L^T h + w||^2 for two row-pairs.
// C layout: per i {w_i, L[i][i..9 col i]}, C[65]=d. Registers: no z array.
// ---------------------------------------------------------------------------
__device__ __forceinline__ void qform10(const float* __restrict__ C,
                                        const ull* hA, const ull* hB,
                                        ull& ossA, ull& ossB)
{
    ull d2 = dup2(C[65]);
    ull sa = d2, sb = d2;
    int k = 0;
    #pragma unroll
    for (int i = 0; i < 10; i++) {
        ull W = dup2(C[k++]);
        ull a = W, b = W;
        #pragma unroll
        for (int j = i; j < 10; j++) {
            W = dup2(C[k++]);
            a = fma2(hA[j], W, a);
            b = fma2(hB[j], W, b);
        }
        sa = fma2(a, a, sa);
        sb = fma2(b, b, sb);
    }
    ossA = sa; ossB = sb;
}

__device__ __forceinline__ float qform10_scalar(const float* __restrict__ C,
                                                const float* h)
{
    float acc = C[65];
    int k = 0;
    #pragma unroll
    for (int i = 0; i < 10; i++) {
        float a = C[k++];
        #pragma unroll
        for (int j = i; j < 10; j++) a = fmaf(h[j], C[k++], a);
        acc = fmaf(a, a, acc);
    }
    return acc;
}

// ---------------------------------------------------------------------------
// Pass 1: one quad (4 rows) per thread; Cholesky quadratic forms; reduction;
// last-finishing block computes mode/invc and resets accumulators.
// ---------------------------------------------------------------------------
__global__ void __launch_bounds__(P1THR, 4)
k_pass1(const float* __restrict__ x,
        const float* __restrict__ sw1, const float* __restrict__ sb1,
        const float* __restrict__ pw1, const float* __restrict__ pb1,
        int n)
{
    __shared__ __align__(16) float A1[40], B1[40], CS[66], CP[66];
    int tid = threadIdx.x;

    for (int i = tid; i < 80; i += P1THR) {
        if (i < 40) {
            int h = i >> 2, c = i & 3;
            A1[i] = (c < 3) ? sw1[c * 10 + h] : sb1[h];
        } else {
            int j = i - 40, h = j >> 2, c = j & 3;
            B1[j] = (c < 3) ? pw1[c * 10 + h] : pb1[h];
        }
    }
    for (int i = tid; i < 132; i += P1THR) {
        if (i < 66) CS[i] = g_CS[i];
        else        CP[i - 66] = g_CP[i - 66];
    }
    __syncthreads();

    float lss = 0.f, lpp = 0.f, lmax = 0.f;

    int nquad = n >> 2;
    int q = blockIdx.x * P1THR + tid;

    if (q < nquad) {
        int r0 = q * 4;
        const float4* xv = (const float4*)(x + (size_t)r0 * 6);
        float4 X0 = xv[0], X1 = xv[1], X2 = xv[2], X3 = xv[3], X4 = xv[4], X5 = xv[5];

        ull hA[10], hB[10];
        const float4* A1v = (const float4*)A1;
        const float4* B1v = (const float4*)B1;

        // ---- s branch: layer1 scalar, pack, quadratic form ----
        #pragma unroll
        for (int h = 0; h < 10; h++) {
            float4 w = A1v[h];
            float t0 = fmaxf(fmaf(X0.z, w.z, fmaf(X0.y, w.y, fmaf(X0.x, w.x, w.w))), 0.f);
            float t1 = fmaxf(fmaf(X2.x, w.z, fmaf(X1.w, w.y, fmaf(X1.z, w.x, w.w))), 0.f);
            float t2 = fmaxf(fmaf(X3.z, w.z, fmaf(X3.y, w.y, fmaf(X3.x, w.x, w.w))), 0.f);
            float t3 = fmaxf(fmaf(X5.x, w.z, fmaf(X4.w, w.y, fmaf(X4.z, w.x, w.w))), 0.f);
            hA[h] = pk2(t0, t1); hB[h] = pk2(t2, t3);
        }
        ull ssa, ssb;
        qform10(CS, hA, hB, ssa, ssb);

        // ---- p branch ----
        #pragma unroll
        for (int h = 0; h < 10; h++) {
            float4 u = B1v[h];
            float t0 = fmaxf(fmaf(X1.y, u.z, fmaf(X1.x, u.y, fmaf(X0.w, u.x, u.w))), 0.f);
            float t1 = fmaxf(fmaf(X2.w, u.z, fmaf(X2.z, u.y, fmaf(X2.y, u.x, u.w))), 0.f);
            float t2 = fmaxf(fmaf(X4.y, u.z, fmaf(X4.x, u.y, fmaf(X3.w, u.x, u.w))), 0.f);
            float t3 = fmaxf(fmaf(X5.w, u.z, fmaf(X5.z, u.y, fmaf(X5.y, u.x, u.w))), 0.f);
            hA[h] = pk2(t0, t1); hB[h] = pk2(t2, t3);
        }
        ull ppa, ppb;
        qform10(CP, hA, hB, ppa, ppb);

        // ---- reduce this quad ----
        float a, b;
        upk2(ssa, a, b); lss = a + b;
        upk2(ssb, a, b); lss += a + b;
        upk2(ppa, a, b); lpp = a + b;
        upk2(ppb, a, b); lpp += a + b;
        ull pra = mul2(ssa, ppa), prb = mul2(ssb, ppb);
        upk2(pra, a, b); lmax = fmaxf(a, b);
        upk2(prb, a, b); lmax = fmaxf(lmax, fmaxf(a, b));
    }

    // scalar tail rows (n % 4) in block 0
    int tail = n & 3;
    if (blockIdx.x == 0 && tid < tail) {
        int r = (n & ~3) + tid;
        float xs[6];
        #pragma unroll
        for (int j = 0; j < 6; j++) xs[j] = x[(size_t)r * 6 + j];
        const float4* A1v = (const float4*)A1;
        const float4* B1v = (const float4*)B1;
        float hs[10], hp[10];
        #pragma unroll
        for (int h = 0; h < 10; h++) {
            float4 w = A1v[h];
            hs[h] = fmaxf(fmaf(xs[2], w.z, fmaf(xs[1], w.y, fmaf(xs[0], w.x, w.w))), 0.f);
            float4 u = B1v[h];
            hp[h] = fmaxf(fmaf(xs[5], u.z, fmaf(xs[4], u.y, fmaf(xs[3], u.x, u.w))), 0.f);
        }
        float ssr = qform10_scalar(CS, hs);
        float ppr = qform10_scalar(CP, hp);
        lss += ssr; lpp += ppr;
        lmax = fmaxf(lmax, ssr * ppr);
    }

    // ---- reduction + last-block finalize ----
    #pragma unroll
    for (int o = 16; o > 0; o >>= 1) {
        lss += __shfl_down_sync(0xffffffffu, lss, o);
        lpp += __shfl_down_sync(0xffffffffu, lpp, o);
        lmax = fmaxf(lmax, __shfl_down_sync(0xffffffffu, lmax, o));
    }
    __shared__ float rs_[4], rp_[4], rm_[4];
    int wid = tid >> 5, lane = tid & 31;
    if (lane == 0) { rs_[wid] = lss; rp_[wid] = lpp; rm_[wid] = lmax; }
    __syncthreads();
    if (tid == 0) {
        float sA = 0.f, sB = 0.f, sM = 0.f;
        #pragma unroll
        for (int w = 0; w < P1THR / 32; w++) {
            sA += rs_[w]; sB += rp_[w]; sM = fmaxf(sM, rm_[w]);
        }
        atomicAdd(&g_ss, (double)sA);
        atomicAdd(&g_pp, (double)sB);
        atomicMax(&g_rowmax_bits, __float_as_uint(sM));

        __threadfence();
        unsigned int old = atomicAdd(&g_count, 1u);
        if (old == gridDim.x - 1) {
            __threadfence();
            float snorm = sqrtf((float)g_ss);
            float pnorm = sqrtf((float)g_pp);
            float c = snorm * pnorm;
            float invc = (c > 0.f) ? (1.0f / c) : 0.0f;
            g_invc = invc;
            // rowmax >= max_row sum_o |s_o p_o|  (Cauchy-Schwarz)
            float rowmax = sqrtf(fmaxf(__uint_as_float(g_rowmax_bits), 0.f));
            float bound1 = rowmax * invc * g_maxabs_ow1;
            int f1 = (c > 0.f && g_minabs_ob1 > 2.0f * bound1);
            float gbound = g_maxabsM * rowmax * invc;
            int f2 = f1 && (gbound < 2.0e-4f * g_minabs_base);
            g_mode = f2 ? 2 : (f1 ? 1 : 0);
            g_ss = 0.0; g_pp = 0.0; g_rowmax_bits = 0u; g_count = 0u;
            __threadfence();
        }
    }
}

// ---------------------------------------------------------------------------
// Fill (mode 2): one wave of blocks, each bulk-copies its chunks.
// ---------------------------------------------------------------------------
__global__ void __launch_bounds__(P2THR)
k_fill(float* __restrict__ out, int n)
{
    if (g_mode != 2) return;
    __shared__ __align__(16) float patbuf[CHUNKF];
    int tid = threadIdx.x;
    float b0 = g_base[0], b1 = g_base[1], b2 = g_base[2];

    float4 P[3];
    P[0] = make_float4(b0, b1, b2, b0);
    P[1] = make_float4(b1, b2, b0, b1);
    P[2] = make_float4(b2, b0, b1, b2);
    float4* p4 = (float4*)patbuf;
    for (int j = tid; j < CHUNKF / 4; j += P2THR) p4[j] = P[j % 3];
    __syncthreads();

    size_t total  = (size_t)n * 3;
    size_t nchunk = (total * 4) / CHUNKB;
    if (tid == 0) {
        asm volatile("fence.proxy.async;" ::: "memory");
        unsigned int saddr;
        asm("{ .reg .u64 t; cvta.to.shared.u64 t, %1; cvt.u32.u64 %0, t; }"
            : "=r"(saddr) : "l"(patbuf));
        for (size_t c = blockIdx.x; c < nchunk; c += gridDim.x) {
            float* dst = out + c * CHUNKF;
            asm volatile(
                "cp.async.bulk.global.shared::cta.bulk_group [%0], [%1], %2;"
                :: "l"(dst), "r"(saddr), "r"((unsigned int)CHUNKB) : "memory");
        }
        asm volatile("cp.async.bulk.commit_group;" ::: "memory");
        asm volatile("cp.async.bulk.wait_group 0;" ::: "memory");
    }
    if (blockIdx.x == 0) {
        float bb[3] = {b0, b1, b2};
        for (size_t i = nchunk * CHUNKF + tid; i < total; i += P2THR)
            out[i] = bb[i % 3];
    }
}

// ---------------------------------------------------------------------------
// Fallback (mode 1 linear / mode 0 exact); early exit in mode 2.
// ---------------------------------------------------------------------------
__global__ void __launch_bounds__(P2THR)
k_fallback(const float* __restrict__ x,
           const float* __restrict__ sw1, const float* __restrict__ sb1,
           const float* __restrict__ sw2, const float* __restrict__ sb2,
           const float* __restrict__ pw1, const float* __restrict__ pb1,
           const float* __restrict__ pw2, const float* __restrict__ pb2,
           const float* __restrict__ ow1, const float* __restrict__ ob1,
           const float* __restrict__ ow2, const float* __restrict__ ob2,
           float* __restrict__ out, int n)
{
    int mode = g_mode;
    if (mode == 2) return;
    int tid = threadIdx.x;
    float invc = g_invc;

    __shared__ __align__(16) float A1[40], B1[40], A2s[120], B2s[120], Ms[32];
    __shared__ float OW1[1000], OB1[100], OW2[300];
    for (int i = tid; i < 80; i += P2THR) {
        if (i < 40) { int h = i >> 2, c = i & 3; A1[i] = (c < 3) ? sw1[c * 10 + h] : sb1[h]; }
        else { int j = i - 40, h = j >> 2, c = j & 3; B1[j] = (c < 3) ? pw1[c * 10 + h] : pb1[h]; }
    }
    for (int i = tid; i < 240; i += P2THR) {
        if (i < 120) { int o = i / 12, c = i - o * 12;
            A2s[i] = (c < 10) ? sw2[c * 10 + o] : ((c == 10) ? sb2[o] : 0.f); }
        else { int j = i - 120, o = j / 12, c = j - o * 12;
            B2s[j] = (c < 10) ? pw2[c * 10 + o] : ((c == 10) ? pb2[o] : 0.f); }
    }
    for (int i = tid; i < 32; i += P2THR) Ms[i] = (i < 30) ? g_M[i] : 0.f;
    if (mode == 0) {
        for (int i = tid; i < 1000; i += P2THR) OW1[i] = ow1[i];
        for (int i = tid; i < 100;  i += P2THR) OB1[i] = ob1[i];
        for (int i = tid; i < 300;  i += P2THR) OW2[i] = ow2[i];
    }
    __syncthreads();
    float c0, c1, c2;
    if (mode == 0) { c0 = ob2[0]; c1 = ob2[1]; c2 = ob2[2]; }
    else           { c0 = g_base[0]; c1 = g_base[1]; c2 = g_base[2]; }

    int stride = gridDim.x * blockDim.x;
    for (int r = blockIdx.x * blockDim.x + tid; r < n; r += stride) {
        const float2* xr = reinterpret_cast<const float2*>(x + (size_t)r * 6);
        float2 u0 = xr[0], u1 = xr[1], u2 = xr[2];
        float h1s[10], h1p[10];
        const float4* A1v = (const float4*)A1;
        const float4* B1v = (const float4*)B1;
        #pragma unroll
        for (int h = 0; h < 10; h++) {
            float4 w = A1v[h];
            h1s[h] = fmaxf(fmaf(u1.x, w.z, fmaf(u0.y, w.y, fmaf(u0.x, w.x, w.w))), 0.f);
            float4 u = B1v[h];
            h1p[h] = fmaxf(fmaf(u2.y, u.z, fmaf(u2.x, u.y, fmaf(u1.y, u.x, u.w))), 0.f);
        }
        float sp[10];
        #pragma unroll
        for (int o = 0; o < 10; o++) {
            const float* av = A2s + 12 * o;
            const float* bv = B2s + 12 * o;
            float sa = av[10], pa = bv[10];
            #pragma unroll
            for (int h = 0; h < 10; h++) {
                sa = fmaf(h1s[h], av[h], sa);
                pa = fmaf(h1p[h], bv[h], pa);
            }
            sp[o] = sa * pa;
        }
        if (mode == 1) {
            float a0 = c0, a1 = c1, a2 = c2;
            #pragma unroll
            for (int o = 0; o < 10; o++) {
                float v = sp[o] * invc;
                a0 = fmaf(v, Ms[3 * o + 0], a0);
                a1 = fmaf(v, Ms[3 * o + 1], a1);
                a2 = fmaf(v, Ms[3 * o + 2], a2);
            }
            out[3 * r + 0] = a0; out[3 * r + 1] = a1; out[3 * r + 2] = a2;
        } else {
            float tf[10];
            #pragma unroll
            for (int o = 0; o < 10; o++) tf[o] = sp[o] * invc;
            float a0 = c0, a1 = c1, a2 = c2;
            #pragma unroll 2
            for (int j = 0; j < 100; j++) {
                float hj = OB1[j];
                #pragma unroll
                for (int o = 0; o < 10; o++)
                    hj = fmaf(tf[o], OW1[o * 100 + j], hj);
                hj = fmaxf(hj, 0.f);
                a0 = fmaf(hj, OW2[3 * j + 0], a0);
                a1 = fmaf(hj, OW2[3 * j + 1], a1);
                a2 = fmaf(hj, OW2[3 * j + 2], a2);
            }
            out[3 * r + 0] = a0; out[3 * r + 1] = a1; out[3 * r + 2] = a2;
        }
    }
}

// ---------------------------------------------------------------------------
extern "C" void kernel_launch(void* const* d_in, const int* in_sizes, int n_in,
                              void* d_out, int out_size)
{
    const float* x   = (const float*)d_in[0];
    const float* sw1 = (const float*)d_in[1];
    const float* sb1 = (const float*)d_in[2];
    const float* sw2 = (const float*)d_in[3];
    const float* sb2 = (const float*)d_in[4];
    const float* pw1 = (const float*)d_in[5];
    const float* pb1 = (const float*)d_in[6];
    const float* pw2 = (const float*)d_in[7];
    const float* pb2 = (const float*)d_in[8];
    const float* ow1 = (const float*)d_in[9];
    const float* ob1 = (const float*)d_in[10];
    const float* ow2 = (const float*)d_in[11];
    const float* ob2 = (const float*)d_in[12];
    float* out = (float*)d_out;

    int n = in_sizes[0] / 6;
    if (n > MAXN) n = MAXN;

    int nquad  = n >> 2;
    int rowblk = (nquad + P1THR - 1) / P1THR;
    if (rowblk < 1) rowblk = 1;

    k_setup<<<1, 128>>>(sw2, sb2, pw2, pb2, ow1, ob1, ow2, ob2);
    k_pass1<<<rowblk, P1THR>>>(x, sw1, sb1, pw1, pb1, n);
    k_fill<<<FILLBLK, P2THR>>>(out, n);
    k_fallback<<<FBBLK, P2THR>>>(x, sw1, sb1, sw2, sb2, pw1, pb1, pw2, pb2,
                                 ow1, ob1, ow2, ob2, out, n);
}